// round 1
// baseline (speedup 1.0000x reference)
#include <cuda_runtime.h>
#include <math.h>

#define NN   4096
#define KF   512     // IN_F
#define CF   512     // OUT_F * N_HEADS
#define NH   8
#define OF   64

// ---- scratch (device globals; no allocation allowed) ----
__device__ float    g_Wh[NN * CF];       // 8 MB
__device__ unsigned g_bits[NN * 128];    // 2 MB packed adj
__device__ float    g_src[NN * NH], g_dst[NN * NH];
__device__ float    g_Es[NN * NH],  g_Es2[NN * NH];
__device__ float    g_Ed[NN * NH],  g_Ed2[NN * NH];

// ============================================================
// Kernel A: Wh = h (4096x512) @ W (512x512), fp32 tiled GEMM
// tile 128x64, BK=16, 256 threads, 8x4 per thread
// ============================================================
__global__ __launch_bounds__(256) void k_gemm_wh(const float* __restrict__ h,
                                                 const float* __restrict__ W) {
    __shared__ float As[16][132];
    __shared__ float Bs[16][68];
    int tid = threadIdx.x;
    int n0 = blockIdx.y * 128;
    int c0 = blockIdx.x * 64;
    float acc[8][4];
#pragma unroll
    for (int r = 0; r < 8; r++)
#pragma unroll
        for (int c = 0; c < 4; c++) acc[r][c] = 0.f;
    int fn = tid & 15, im = tid >> 4;

    for (int k0 = 0; k0 < KF; k0 += 16) {
#pragma unroll
        for (int q = 0; q < 2; q++) {
            int idx = tid + q * 256;
            int n = idx >> 2, kq = (idx & 3) << 2;
            float4 v = *(const float4*)(h + (n0 + n) * KF + k0 + kq);
            As[kq + 0][n] = v.x; As[kq + 1][n] = v.y;
            As[kq + 2][n] = v.z; As[kq + 3][n] = v.w;
        }
        {
            int k = tid >> 4, f4 = (tid & 15) << 2;
            *(float4*)&Bs[k][f4] = *(const float4*)(W + (k0 + k) * CF + c0 + f4);
        }
        __syncthreads();
#pragma unroll
        for (int kk = 0; kk < 16; kk++) {
            float av[8], bv[4];
            *(float4*)&av[0] = *(float4*)&As[kk][im * 8];
            *(float4*)&av[4] = *(float4*)&As[kk][im * 8 + 4];
            *(float4*)&bv[0] = *(float4*)&Bs[kk][fn * 4];
#pragma unroll
            for (int r = 0; r < 8; r++)
#pragma unroll
                for (int c = 0; c < 4; c++)
                    acc[r][c] += av[r] * bv[c];
        }
        __syncthreads();
    }
#pragma unroll
    for (int r = 0; r < 8; r++) {
        float4 v = make_float4(acc[r][0], acc[r][1], acc[r][2], acc[r][3]);
        *(float4*)(g_Wh + (n0 + im * 8 + r) * CF + c0 + fn * 4) = v;
    }
}

// ============================================================
// Kernel B: src/dst = Wh . a_src / a_dst  plus exp tables
// one warp per (node, head)
// ============================================================
__global__ __launch_bounds__(256) void k_pre(const float* __restrict__ a) {
    int n = blockIdx.x;
    int w = threadIdx.x >> 5;
    int lane = threadIdx.x & 31;
    float v0 = g_Wh[n * CF + w * OF + lane];
    float v1 = g_Wh[n * CF + w * OF + 32 + lane];
    float s = v0 * a[lane] + v1 * a[lane + 32];
    float d = v0 * a[64 + lane] + v1 * a[96 + lane];
#pragma unroll
    for (int o = 16; o; o >>= 1) {
        s += __shfl_xor_sync(0xFFFFFFFFu, s, o);
        d += __shfl_xor_sync(0xFFFFFFFFu, d, o);
    }
    if (lane == 0) {
        int idx = n * NH + w;
        g_src[idx] = s;            g_dst[idx] = d;
        g_Es[idx]  = expf(s);      g_Es2[idx] = expf(0.2f * s);
        g_Ed[idx]  = expf(d);      g_Ed2[idx] = expf(0.2f * d);
    }
}

// ============================================================
// Kernel P: pack adj (int32 0/1) into bitmask, 1 bit per edge
// ============================================================
__global__ __launch_bounds__(256) void k_pack(const int* __restrict__ adj) {
    int i = blockIdx.x;
    int w = threadIdx.x >> 5, lane = threadIdx.x & 31;
#pragma unroll
    for (int q = 0; q < 16; q++) {
        int wd = w * 16 + q;                 // word 0..127
        int j = wd * 32 + lane;
        unsigned b = __ballot_sync(0xFFFFFFFFu, adj[i * NN + j] > 0);
        if (lane == 0) g_bits[i * 128 + wd] = b;
    }
}

// ============================================================
// Kernel C: fused masked-softmax attention aggregate + ELU
// CTA = 256 i-rows x 1 head. TJ=64. Z accumulated in-GEMM.
// ============================================================
#define SSTRIDE 260
#define WSTRIDE 68
#define SMEM_C ((64 * SSTRIDE + 64 * WSTRIDE + 256 * 4) * 4 + 256 * 2 * 4)

__global__ __launch_bounds__(256) void k_gat(float* __restrict__ out) {
    extern __shared__ float sm[];
    float* Ssm  = sm;                       // [64][260] score tile (j-major)
    float* Wsm  = Ssm + 64 * SSTRIDE;       // [64][68]  Wh tile
    float* srcA = Wsm + 64 * WSTRIDE;       // [256]
    float* EsA  = srcA + 256;
    float* Es2A = EsA + 256;
    float* zsm  = Es2A + 256;               // [256]
    unsigned* bitsm = (unsigned*)(zsm + 256); // [256][2]

    int tid  = threadIdx.x;
    int head = blockIdx.x;
    int i0   = blockIdx.y << 8;

    {
        int idx = (i0 + tid) * NH + head;
        srcA[tid] = g_src[idx];
        EsA[tid]  = g_Es[idx];
        Es2A[tid] = g_Es2[idx];
    }

    float acc[8][8];
#pragma unroll
    for (int r = 0; r < 8; r++)
#pragma unroll
        for (int c = 0; c < 8; c++) acc[r][c] = 0.f;
    float zacc[8] = {0.f, 0.f, 0.f, 0.f, 0.f, 0.f, 0.f, 0.f};

    int fi = tid & 7, ii = tid >> 3;        // GEMM mapping: 8f x 8i per thread
    int jl = tid & 63;                      // score-gen: fixed local j
    int ig = (tid >> 6) << 2;               // score-gen: i sub-offset
    int wsel = jl >> 5, bpos = jl & 31;

    for (int j0 = 0; j0 < NN; j0 += 64) {
        int jg = (j0 + jl) * NH + head;
        float dstj = g_dst[jg], Edj = g_Ed[jg], Ed2j = g_Ed2[jg];

        __syncthreads();   // previous GEMM done reading smem tiles
        {
            uint2 b = *(const uint2*)(g_bits + (i0 + tid) * 128 + (j0 >> 5));
            bitsm[tid * 2] = b.x; bitsm[tid * 2 + 1] = b.y;
        }
#pragma unroll
        for (int q = 0; q < 4; q++) {
            int lin = tid + q * 256;
            int j = lin >> 4, f4 = (lin & 15) << 2;
            *(float4*)&Wsm[j * WSTRIDE + f4] =
                *(const float4*)(g_Wh + (j0 + j) * CF + head * OF + f4);
        }
        __syncthreads();   // bits + Wh tile visible

        // score generation: p = adj ? (e>0 ? Es_i*Ed_j : Es2_i*Ed2_j) : 0
#pragma unroll
        for (int it = 0; it < 16; it++) {
            int ib = it * 16 + ig;
            float4 sv;
#pragma unroll
            for (int k = 0; k < 4; k++) {
                int i = ib + k;
                unsigned wd = bitsm[i * 2 + wsel];
                float t = srcA[i] + dstj;
                float p = (t > 0.f) ? (EsA[i] * Edj) : (Es2A[i] * Ed2j);
                p = ((wd >> bpos) & 1u) ? p : 0.f;
                ((float*)&sv)[k] = p;
            }
            *(float4*)&Ssm[jl * SSTRIDE + ib] = sv;
        }
        __syncthreads();   // S tile visible

        // acc[256x64] += S[256x64] @ Wh[64x64]; fi==0 also sums Z rows
#pragma unroll 8
        for (int kk = 0; kk < 64; kk++) {
            float sA[8], sB[8];
            *(float4*)&sA[0] = *(float4*)&Ssm[kk * SSTRIDE + ii * 8];
            *(float4*)&sA[4] = *(float4*)&Ssm[kk * SSTRIDE + ii * 8 + 4];
            *(float4*)&sB[0] = *(float4*)&Wsm[kk * WSTRIDE + fi * 8];
            *(float4*)&sB[4] = *(float4*)&Wsm[kk * WSTRIDE + fi * 8 + 4];
#pragma unroll
            for (int r = 0; r < 8; r++)
#pragma unroll
                for (int c = 0; c < 8; c++)
                    acc[r][c] += sA[r] * sB[c];
            if (fi == 0) {
#pragma unroll
                for (int r = 0; r < 8; r++) zacc[r] += sA[r];
            }
        }
    }

    __syncthreads();
    if (fi == 0) {
#pragma unroll
        for (int r = 0; r < 8; r++) zsm[ii * 8 + r] = zacc[r];
    }
    __syncthreads();

    // epilogue: divide by Z, ELU, store
#pragma unroll
    for (int r = 0; r < 8; r++) {
        float inv = 1.0f / zsm[ii * 8 + r];
        float o[8];
#pragma unroll
        for (int c = 0; c < 8; c++) {
            float v = acc[r][c] * inv;
            o[c] = v > 0.f ? v : (expf(v) - 1.0f);
        }
        float* dst = out + (i0 + ii * 8 + r) * CF + head * OF + fi * 8;
        *(float4*)dst       = *(float4*)&o[0];
        *(float4*)(dst + 4) = *(float4*)&o[4];
    }
}

// ============================================================
extern "C" void kernel_launch(void* const* d_in, const int* in_sizes, int n_in,
                              void* d_out, int out_size) {
    const float* h   = (const float*)d_in[0];
    const int*   adj = (const int*)d_in[1];
    const float* W   = (const float*)d_in[2];
    const float* a   = (const float*)d_in[3];
    float* out = (float*)d_out;

    k_gemm_wh<<<dim3(8, 32), 256>>>(h, W);
    k_pack<<<NN, 256>>>(adj);
    k_pre<<<NN, 256>>>(a);

    cudaFuncSetAttribute(k_gat, cudaFuncAttributeMaxDynamicSharedMemorySize, SMEM_C);
    k_gat<<<dim3(NH, NN / 256), 256, SMEM_C>>>(out);
}

// round 4
// speedup vs baseline: 1.6836x; 1.6836x over previous
#include <cuda_runtime.h>
#include <cuda_fp16.h>
#include <math.h>
#include <stdint.h>

#define NN   4096
#define KF   512     // IN_F
#define CF   512     // OUT_F * N_HEADS
#define NH   8
#define OF   64

// ---- scratch (device globals; no allocation allowed) ----
__device__ float    g_Wh[NN * CF];          // 8 MB fp32 (exact, feeds src/dst)
__device__ __half   g_WhT[NH * OF * NN];    // 4 MB fp16 transposed values [h][f][n]
__device__ unsigned g_bits[NN * 128];       // 2 MB packed adj
__device__ float4   g_attrS[NH * NN];       // (src, Es/16, Es2/16, 0) head-major
__device__ float4   g_attrD[NH * NN];       // (dst, Ed,    Ed2,    0) head-major

__device__ __forceinline__ uint32_t smem_u32(const void* p) {
    uint32_t a;
    asm("{ .reg .u64 t; cvta.to.shared.u64 t, %1; cvt.u32.u64 %0, t; }" : "=r"(a) : "l"(p));
    return a;
}
__device__ __forceinline__ void ldsm4(uint32_t& r0, uint32_t& r1, uint32_t& r2, uint32_t& r3,
                                      uint32_t addr) {
    asm volatile("ldmatrix.sync.aligned.m8n8.x4.shared.b16 {%0,%1,%2,%3}, [%4];"
                 : "=r"(r0), "=r"(r1), "=r"(r2), "=r"(r3) : "r"(addr));
}
__device__ __forceinline__ void mma16816(float* d, const uint32_t* a, const uint32_t* b) {
    asm volatile(
        "mma.sync.aligned.m16n8k16.row.col.f32.f16.f16.f32 "
        "{%0,%1,%2,%3}, {%4,%5,%6,%7}, {%8,%9}, {%0,%1,%2,%3};"
        : "+f"(d[0]), "+f"(d[1]), "+f"(d[2]), "+f"(d[3])
        : "r"(a[0]), "r"(a[1]), "r"(a[2]), "r"(a[3]), "r"(b[0]), "r"(b[1]));
}

// ============================================================
// Kernel A: Wh = h @ W, fp32 tiled GEMM
// ============================================================
__global__ __launch_bounds__(256) void k_gemm_wh(const float* __restrict__ h,
                                                 const float* __restrict__ W) {
    __shared__ float As[16][132];
    __shared__ float Bs[16][68];
    int tid = threadIdx.x;
    int n0 = blockIdx.y * 128;
    int c0 = blockIdx.x * 64;
    float acc[8][4];
#pragma unroll
    for (int r = 0; r < 8; r++)
#pragma unroll
        for (int c = 0; c < 4; c++) acc[r][c] = 0.f;
    int fn = tid & 15, im = tid >> 4;

    for (int k0 = 0; k0 < KF; k0 += 16) {
#pragma unroll
        for (int q = 0; q < 2; q++) {
            int idx = tid + q * 256;
            int n = idx >> 2, kq = (idx & 3) << 2;
            float4 v = *(const float4*)(h + (n0 + n) * KF + k0 + kq);
            As[kq + 0][n] = v.x; As[kq + 1][n] = v.y;
            As[kq + 2][n] = v.z; As[kq + 3][n] = v.w;
        }
        {
            int k = tid >> 4, f4 = (tid & 15) << 2;
            *(float4*)&Bs[k][f4] = *(const float4*)(W + (k0 + k) * CF + c0 + f4);
        }
        __syncthreads();
#pragma unroll
        for (int kk = 0; kk < 16; kk++) {
            float av[8], bv[4];
            *(float4*)&av[0] = *(float4*)&As[kk][im * 8];
            *(float4*)&av[4] = *(float4*)&As[kk][im * 8 + 4];
            *(float4*)&bv[0] = *(float4*)&Bs[kk][fn * 4];
#pragma unroll
            for (int r = 0; r < 8; r++)
#pragma unroll
                for (int c = 0; c < 4; c++)
                    acc[r][c] += av[r] * bv[c];
        }
        __syncthreads();
    }
#pragma unroll
    for (int r = 0; r < 8; r++) {
        float4 v = make_float4(acc[r][0], acc[r][1], acc[r][2], acc[r][3]);
        *(float4*)(g_Wh + (n0 + im * 8 + r) * CF + c0 + fn * 4) = v;
    }
}

// ============================================================
// Kernel T: g_WhT[h][f][n] = fp16(g_Wh[n][h*64+f])
// ============================================================
__global__ __launch_bounds__(256) void k_transpose() {
    __shared__ __half Ts[64 * 130];
    int h = blockIdx.x, n0 = blockIdx.y * 128;
    int tid = threadIdx.x;
#pragma unroll
    for (int q = 0; q < 32; q++) {
        int lin = tid + q * 256;
        int r = lin >> 6, c = lin & 63;
        Ts[c * 130 + r] = __float2half(g_Wh[(n0 + r) * CF + h * OF + c]);
    }
    __syncthreads();
#pragma unroll
    for (int q = 0; q < 16; q++) {
        int lin = tid + q * 256;
        int f = lin >> 6, n2 = lin & 63;
        __half2 hv = __halves2half2(Ts[f * 130 + n2 * 2], Ts[f * 130 + n2 * 2 + 1]);
        *(__half2*)&g_WhT[(h * OF + f) * NN + n0 + n2 * 2] = hv;
    }
}

// ============================================================
// Kernel B: per (node,head) src/dst + exp tables (head-major float4)
// Es scaled by 1/16 (cancels in softmax ratio; fp16 headroom)
// ============================================================
__global__ __launch_bounds__(256) void k_pre(const float* __restrict__ a) {
    int n = blockIdx.x;
    int w = threadIdx.x >> 5;
    int lane = threadIdx.x & 31;
    float v0 = g_Wh[n * CF + w * OF + lane];
    float v1 = g_Wh[n * CF + w * OF + 32 + lane];
    float s = v0 * a[lane] + v1 * a[lane + 32];
    float d = v0 * a[64 + lane] + v1 * a[96 + lane];
#pragma unroll
    for (int o = 16; o; o >>= 1) {
        s += __shfl_xor_sync(0xFFFFFFFFu, s, o);
        d += __shfl_xor_sync(0xFFFFFFFFu, d, o);
    }
    if (lane == 0) {
        g_attrS[w * NN + n] = make_float4(s, expf(s) * 0.0625f, expf(0.2f * s) * 0.0625f, 0.f);
        g_attrD[w * NN + n] = make_float4(d, expf(d), expf(0.2f * d), 0.f);
    }
}

// ============================================================
// Kernel P: pack adj into bitmask
// ============================================================
__global__ __launch_bounds__(256) void k_pack(const int* __restrict__ adj) {
    int i = blockIdx.x;
    int w = threadIdx.x >> 5, lane = threadIdx.x & 31;
#pragma unroll
    for (int q = 0; q < 16; q++) {
        int wd = w * 16 + q;
        int j = wd * 32 + lane;
        unsigned b = __ballot_sync(0xFFFFFFFFu, adj[i * NN + j] > 0);
        if (lane == 0) g_bits[i * 128 + wd] = b;
    }
}

// ============================================================
// Kernel C: fused attention, mma.sync HMMA (m16n8k16 f16->f32)
// CTA = 128 i-rows x 1 head, 256 threads = 8 warps,
// warp w owns i-rows [w*16, w*16+16), j-steps of 64
// ============================================================
#define SSTR 72                      // S row stride in halves (144 B)
#define BSTR 72                      // B row stride in halves
#define SM_S    0                    // 128*72*2 = 18432
#define SM_B    18432                // 64*72*2  = 9216
#define SM_JATT 27648                // 64*16    = 1024
#define SM_Z    28672                // 128*4    = 512
#define SM_TOT  29184

__global__ __launch_bounds__(256, 2) void k_gat_mma(float* __restrict__ out) {
    extern __shared__ char sm[];
    uint32_t sb = smem_u32(sm);
    __half* Ssm = (__half*)(sm + SM_S);
    __half* Bs  = (__half*)(sm + SM_B);
    float4* jatt = (float4*)(sm + SM_JATT);
    float*  zsm  = (float*)(sm + SM_Z);

    int tid = threadIdx.x, wid = tid >> 5, lane = tid & 31;
    int head = blockIdx.x, i0 = blockIdx.y << 7;

    // score-gen mapping: thread owns rows quad*4..+3, j-group jg (8 j's)
    int jg = tid & 7, quad = tid >> 3;
    float4 aS[4];
#pragma unroll
    for (int r = 0; r < 4; r++)
        aS[r] = g_attrS[head * NN + i0 + quad * 4 + r];
    float z4[4] = {0.f, 0.f, 0.f, 0.f};

    // mma accumulators: warp computes D[16][64] = 8 n-tiles x 4 regs
    float acc[8][4];
#pragma unroll
    for (int nt = 0; nt < 8; nt++)
#pragma unroll
        for (int q = 0; q < 4; q++) acc[nt][q] = 0.f;

    // ldmatrix addresses (byte offsets in shared)
    // A (S tile): lanes 0-15 -> rows, lanes 16-31 -> +16B (k 8..15)
    uint32_t aAddrBase = sb + SM_S + (wid * 16 + (lane & 15)) * (SSTR * 2) + (lane >> 4) * 16;
    // B: n-row = (lane&7) + ((lane>>4)&1)*8 ; k halfsel = (lane>>3)&1
    uint32_t bAddrBase = sb + SM_B + (((lane & 7) + ((lane >> 4) & 1) * 8)) * (BSTR * 2)
                       + ((lane >> 3) & 1) * 16;

    for (int s = 0; s < 64; s++) {
        int j0 = s << 6;

        __syncthreads();   // previous iteration's mma done reading Ssm/Bs

        // stage j attributes
        if (tid < 64) jatt[tid] = g_attrD[head * NN + j0 + tid];
        // stage B tile: Bs[f][j] = WhT[head][f][j0+j], 64x64 halves
#pragma unroll
        for (int q = 0; q < 2; q++) {
            int lin = tid + q * 256;
            int f = lin >> 3, c = lin & 7;        // 64 f x 8 chunks of 8 halves
            uint4 v = *(const uint4*)&g_WhT[(head * OF + f) * NN + j0 + c * 8];
            *(uint4*)&Bs[f * BSTR + c * 8] = v;
        }
        // adjacency bits: this thread's 4 rows, its 32-j window
        unsigned bw[4];
        int wrd = (j0 >> 5) + (jg >> 2);
#pragma unroll
        for (int r = 0; r < 4; r++)
            bw[r] = g_bits[(i0 + quad * 4 + r) * 128 + wrd];

        __syncthreads();   // jatt + B tile visible

        // generate S tile: p = adj ? (e>0 ? Es*Ed : Es2*Ed2) : 0, fp16
        int jb = jg * 8;
        int bitb = (jg & 3) * 8;
#pragma unroll
        for (int k = 0; k < 4; k++) {
            float4 A0 = jatt[jb + 2 * k];
            float4 A1 = jatt[jb + 2 * k + 1];
#pragma unroll
            for (int r = 0; r < 4; r++) {
                float t0 = aS[r].x + A0.x;
                float t1 = aS[r].x + A1.x;
                float p0 = (t0 > 0.f) ? aS[r].y * A0.y : aS[r].z * A0.z;
                float p1 = (t1 > 0.f) ? aS[r].y * A1.y : aS[r].z * A1.z;
                if (!((bw[r] >> (bitb + 2 * k)) & 1u))     p0 = 0.f;
                if (!((bw[r] >> (bitb + 2 * k + 1)) & 1u)) p1 = 0.f;
                __half2 hp = __floats2half2_rn(p0, p1);
                float2 pf = __half22float2(hp);
                z4[r] += pf.x + pf.y;   // Z from the same rounded values the MMA sees
                *(__half2*)&Ssm[(quad * 4 + r) * SSTR + jb + 2 * k] = hp;
            }
        }
        __syncthreads();   // S tile visible

        // warp GEMM: acc[16x64] += S[16x64] @ B[64x64] (Bs n-major)
#pragma unroll
        for (int kc = 0; kc < 4; kc++) {
            uint32_t a[4];
            ldsm4(a[0], a[1], a[2], a[3], aAddrBase + kc * 32);
            uint32_t b[16];
#pragma unroll
            for (int nq = 0; nq < 4; nq++)
                ldsm4(b[nq * 4], b[nq * 4 + 1], b[nq * 4 + 2], b[nq * 4 + 3],
                      bAddrBase + nq * 16 * (BSTR * 2) + kc * 32);
#pragma unroll
            for (int nt = 0; nt < 8; nt++)
                mma16816(acc[nt], a, &b[nt * 2]);
        }
    }

    // Z reduction across 8 jg lanes (low 3 bits of lane)
#pragma unroll
    for (int o = 4; o; o >>= 1)
#pragma unroll
        for (int r = 0; r < 4; r++)
            z4[r] += __shfl_xor_sync(0xFFFFFFFFu, z4[r], o);
    if (jg == 0) {
#pragma unroll
        for (int r = 0; r < 4; r++) zsm[quad * 4 + r] = z4[r];
    }
    __syncthreads();

    // epilogue: normalize, ELU, store. Acc layout: thread t of warp:
    // rows t/4 and t/4+8 (warp-local), cols nt*8 + (t%4)*2 + {0,1}
    {
        int r0 = wid * 16 + (lane >> 2);
        float inv0 = 1.0f / zsm[r0];
        float inv1 = 1.0f / zsm[r0 + 8];
        float* o0 = out + (size_t)(i0 + r0) * CF + head * OF + (lane & 3) * 2;
        float* o1 = o0 + 8 * CF;
#pragma unroll
        for (int nt = 0; nt < 8; nt++) {
            float v0 = acc[nt][0] * inv0, v1 = acc[nt][1] * inv0;
            float v2 = acc[nt][2] * inv1, v3 = acc[nt][3] * inv1;
            v0 = v0 > 0.f ? v0 : (expf(v0) - 1.0f);
            v1 = v1 > 0.f ? v1 : (expf(v1) - 1.0f);
            v2 = v2 > 0.f ? v2 : (expf(v2) - 1.0f);
            v3 = v3 > 0.f ? v3 : (expf(v3) - 1.0f);
            *(float2*)(o0 + nt * 8) = make_float2(v0, v1);
            *(float2*)(o1 + nt * 8) = make_float2(v2, v3);
        }
    }
}

// ============================================================
extern "C" void kernel_launch(void* const* d_in, const int* in_sizes, int n_in,
                              void* d_out, int out_size) {
    const float* h   = (const float*)d_in[0];
    const int*   adj = (const int*)d_in[1];
    const float* W   = (const float*)d_in[2];
    const float* a   = (const float*)d_in[3];
    float* out = (float*)d_out;

    k_gemm_wh<<<dim3(8, 32), 256>>>(h, W);
    k_pack<<<NN, 256>>>(adj);
    k_pre<<<NN, 256>>>(a);
    k_transpose<<<dim3(NH, 32), 256>>>();

    cudaFuncSetAttribute(k_gat_mma, cudaFuncAttributeMaxDynamicSharedMemorySize, SM_TOT);
    k_gat_mma<<<dim3(NH, NN / 128), 256, SM_TOT>>>(out);
}

// round 5
// speedup vs baseline: 1.7816x; 1.0582x over previous
#include <cuda_runtime.h>
#include <cuda_fp16.h>
#include <math.h>
#include <stdint.h>

#define NN   4096
#define KF   512     // IN_F
#define CF   512     // OUT_F * N_HEADS
#define NH   8
#define OF   64

// ---- scratch (device globals; no allocation allowed) ----
__device__ float    g_Wh[NN * CF];          // 8 MB fp32 (exact, feeds src/dst)
__device__ __half   g_WhT[NH * OF * NN];    // 4 MB fp16 transposed values [h][f][n]
__device__ unsigned g_bits[NN * 128];       // 2 MB packed adj
__device__ float4   g_attrS[NH * NN];       // (src, Es/16, Es2/16, 0) head-major
__device__ float4   g_attrD[NH * NN];       // (dst, Ed,    Ed2,    0) head-major

__device__ __forceinline__ uint32_t smem_u32(const void* p) {
    uint32_t a;
    asm("{ .reg .u64 t; cvta.to.shared.u64 t, %1; cvt.u32.u64 %0, t; }" : "=r"(a) : "l"(p));
    return a;
}
__device__ __forceinline__ void ldsm4(uint32_t& r0, uint32_t& r1, uint32_t& r2, uint32_t& r3,
                                      uint32_t addr) {
    asm volatile("ldmatrix.sync.aligned.m8n8.x4.shared.b16 {%0,%1,%2,%3}, [%4];"
                 : "=r"(r0), "=r"(r1), "=r"(r2), "=r"(r3) : "r"(addr));
}
__device__ __forceinline__ void mma16816(float* d, const uint32_t* a, const uint32_t* b) {
    asm volatile(
        "mma.sync.aligned.m16n8k16.row.col.f32.f16.f16.f32 "
        "{%0,%1,%2,%3}, {%4,%5,%6,%7}, {%8,%9}, {%0,%1,%2,%3};"
        : "+f"(d[0]), "+f"(d[1]), "+f"(d[2]), "+f"(d[3])
        : "r"(a[0]), "r"(a[1]), "r"(a[2]), "r"(a[3]), "r"(b[0]), "r"(b[1]));
}

// ============================================================
// Kernel A: Wh = h @ W, fp32 tiled GEMM
// ============================================================
__global__ __launch_bounds__(256) void k_gemm_wh(const float* __restrict__ h,
                                                 const float* __restrict__ W) {
    __shared__ float As[16][132];
    __shared__ float Bs[16][68];
    int tid = threadIdx.x;
    int n0 = blockIdx.y * 128;
    int c0 = blockIdx.x * 64;
    float acc[8][4];
#pragma unroll
    for (int r = 0; r < 8; r++)
#pragma unroll
        for (int c = 0; c < 4; c++) acc[r][c] = 0.f;
    int fn = tid & 15, im = tid >> 4;

    for (int k0 = 0; k0 < KF; k0 += 16) {
#pragma unroll
        for (int q = 0; q < 2; q++) {
            int idx = tid + q * 256;
            int n = idx >> 2, kq = (idx & 3) << 2;
            float4 v = *(const float4*)(h + (n0 + n) * KF + k0 + kq);
            As[kq + 0][n] = v.x; As[kq + 1][n] = v.y;
            As[kq + 2][n] = v.z; As[kq + 3][n] = v.w;
        }
        {
            int k = tid >> 4, f4 = (tid & 15) << 2;
            *(float4*)&Bs[k][f4] = *(const float4*)(W + (k0 + k) * CF + c0 + f4);
        }
        __syncthreads();
#pragma unroll
        for (int kk = 0; kk < 16; kk++) {
            float av[8], bv[4];
            *(float4*)&av[0] = *(float4*)&As[kk][im * 8];
            *(float4*)&av[4] = *(float4*)&As[kk][im * 8 + 4];
            *(float4*)&bv[0] = *(float4*)&Bs[kk][fn * 4];
#pragma unroll
            for (int r = 0; r < 8; r++)
#pragma unroll
                for (int c = 0; c < 4; c++)
                    acc[r][c] += av[r] * bv[c];
        }
        __syncthreads();
    }
#pragma unroll
    for (int r = 0; r < 8; r++) {
        float4 v = make_float4(acc[r][0], acc[r][1], acc[r][2], acc[r][3]);
        *(float4*)(g_Wh + (n0 + im * 8 + r) * CF + c0 + fn * 4) = v;
    }
}

// ============================================================
// Kernel T: g_WhT[h][f][n] = fp16(g_Wh[n][h*64+f])
// ============================================================
__global__ __launch_bounds__(256) void k_transpose() {
    __shared__ __half Ts[64 * 130];
    int h = blockIdx.x, n0 = blockIdx.y * 128;
    int tid = threadIdx.x;
#pragma unroll
    for (int q = 0; q < 32; q++) {
        int lin = tid + q * 256;
        int r = lin >> 6, c = lin & 63;
        Ts[c * 130 + r] = __float2half(g_Wh[(n0 + r) * CF + h * OF + c]);
    }
    __syncthreads();
#pragma unroll
    for (int q = 0; q < 16; q++) {
        int lin = tid + q * 256;
        int f = lin >> 6, n2 = lin & 63;
        __half2 hv = __halves2half2(Ts[f * 130 + n2 * 2], Ts[f * 130 + n2 * 2 + 1]);
        *(__half2*)&g_WhT[(h * OF + f) * NN + n0 + n2 * 2] = hv;
    }
}

// ============================================================
// Kernel B: per (node,head) src/dst + exp tables (head-major float4)
// Es scaled by 1/16 (cancels in softmax ratio; fp16 headroom)
// ============================================================
__global__ __launch_bounds__(256) void k_pre(const float* __restrict__ a) {
    int n = blockIdx.x;
    int w = threadIdx.x >> 5;
    int lane = threadIdx.x & 31;
    float v0 = g_Wh[n * CF + w * OF + lane];
    float v1 = g_Wh[n * CF + w * OF + 32 + lane];
    float s = v0 * a[lane] + v1 * a[lane + 32];
    float d = v0 * a[64 + lane] + v1 * a[96 + lane];
#pragma unroll
    for (int o = 16; o; o >>= 1) {
        s += __shfl_xor_sync(0xFFFFFFFFu, s, o);
        d += __shfl_xor_sync(0xFFFFFFFFu, d, o);
    }
    if (lane == 0) {
        g_attrS[w * NN + n] = make_float4(s, expf(s) * 0.0625f, expf(0.2f * s) * 0.0625f, 0.f);
        g_attrD[w * NN + n] = make_float4(d, expf(d), expf(0.2f * d), 0.f);
    }
}

// ============================================================
// Kernel P: pack adj into bitmask
// ============================================================
__global__ __launch_bounds__(256) void k_pack(const int* __restrict__ adj) {
    int i = blockIdx.x;
    int w = threadIdx.x >> 5, lane = threadIdx.x & 31;
#pragma unroll
    for (int q = 0; q < 16; q++) {
        int wd = w * 16 + q;
        int j = wd * 32 + lane;
        unsigned b = __ballot_sync(0xFFFFFFFFu, adj[i * NN + j] > 0);
        if (lane == 0) g_bits[i * 128 + wd] = b;
    }
}

// ============================================================
// Kernel C: fused attention, mma.sync HMMA, single-barrier pipeline
// CTA = 128 i-rows x 1 head, 8 warps; S/B double-buffered;
// jatt + adjacency bits per-thread registers (no smem staging dep);
// Z = extra mma against ones-column B fragment.
// ============================================================
#define SSTR 72                      // S row stride in halves (144 B)
#define BSTR 72                      // B row stride in halves
#define SBUF 18432                   // 128*72*2 bytes per S buffer
#define BBUF 9216                    // 64*72*2 bytes per B buffer
#define SM_S    0                    // two S buffers: 0, 18432
#define SM_B    36864                // two B buffers: 36864, 46080
#define SM_TOT  55296

__global__ __launch_bounds__(256, 2) void k_gat_mma(float* __restrict__ out) {
    extern __shared__ char sm[];
    uint32_t sb = smem_u32(sm);

    int tid = threadIdx.x, wid = tid >> 5, lane = tid & 31;
    int head = blockIdx.x, i0 = blockIdx.y << 7;

    // score-gen mapping: thread owns rows quad*4..+3, j-group jg (8 j's)
    int jg = tid & 7, quad = tid >> 3;
    float4 aS[4];
#pragma unroll
    for (int r = 0; r < 4; r++)
        aS[r] = g_attrS[head * NN + i0 + quad * 4 + r];
    const float4* attrD = g_attrD + head * NN;
    const unsigned* bitrow[4];
#pragma unroll
    for (int r = 0; r < 4; r++)
        bitrow[r] = g_bits + (size_t)(i0 + quad * 4 + r) * 128;

    // accumulators: 8 n-tiles (64 cols) + 1 z-tile
    float acc[8][4], accz[4];
#pragma unroll
    for (int nt = 0; nt < 8; nt++)
#pragma unroll
        for (int q = 0; q < 4; q++) acc[nt][q] = 0.f;
#pragma unroll
    for (int q = 0; q < 4; q++) accz[q] = 0.f;

    // ones-column B fragment (col 0 = 1.0): lanes with n==0 (lane<4)
    uint32_t bz[2];
    bz[0] = bz[1] = (lane < 4) ? 0x3C003C00u : 0u;

    // ldmatrix byte addresses per buffer
    uint32_t aA[2], bA[2];
    {
        uint32_t aoff = (wid * 16 + (lane & 15)) * (SSTR * 2) + (lane >> 4) * 16;
        uint32_t boff = (((lane & 7) + ((lane >> 4) & 1) * 8)) * (BSTR * 2)
                      + ((lane >> 3) & 1) * 16;
        aA[0] = sb + SM_S + aoff;          aA[1] = aA[0] + SBUF;
        bA[0] = sb + SM_B + boff;          bA[1] = bA[0] + BBUF;
    }

    // ---- stage B tile (64x64 halves) for step s into buffer bufn ----
    auto stageB = [&](int j0, int bufn) {
        __half* Bd = (__half*)(sm + SM_B + bufn * BBUF);
#pragma unroll
        for (int q = 0; q < 2; q++) {
            int lin = tid + q * 256;
            int f = lin >> 3, c = lin & 7;
            uint4 v = *(const uint4*)&g_WhT[(head * OF + f) * NN + j0 + c * 8];
            *(uint4*)&Bd[f * BSTR + c * 8] = v;
        }
    };
    // ---- generate S tile for step s into buffer bufn (register-fed) ----
    auto genS = [&](int j0, int bufn) {
        __half* Sd = (__half*)(sm + SM_S + bufn * SBUF);
        int jb = jg * 8;
        int wrd = (j0 >> 5) + (jg >> 2);
        int bitb = (jg & 3) * 8;
        unsigned bw[4];
#pragma unroll
        for (int r = 0; r < 4; r++) bw[r] = bitrow[r][wrd];
        float4 jA[8];
#pragma unroll
        for (int t = 0; t < 8; t++) jA[t] = attrD[j0 + jb + t];
#pragma unroll
        for (int k = 0; k < 4; k++) {
            float4 A0 = jA[2 * k], A1 = jA[2 * k + 1];
#pragma unroll
            for (int r = 0; r < 4; r++) {
                float t0 = aS[r].x + A0.x;
                float t1 = aS[r].x + A1.x;
                float p0 = (t0 > 0.f) ? aS[r].y * A0.y : aS[r].z * A0.z;
                float p1 = (t1 > 0.f) ? aS[r].y * A1.y : aS[r].z * A1.z;
                if (!((bw[r] >> (bitb + 2 * k)) & 1u))     p0 = 0.f;
                if (!((bw[r] >> (bitb + 2 * k + 1)) & 1u)) p1 = 0.f;
                *(__half2*)&Sd[(quad * 4 + r) * SSTR + jb + 2 * k] = __floats2half2_rn(p0, p1);
            }
        }
    };

    // prologue: fill buffer 0 for step 0
    stageB(0, 0);
    genS(0, 0);

    for (int s = 0; s < 64; s++) {
        int buf = s & 1;
        __syncthreads();                 // buf ready for mma; buf^1 free for writes
        if (s < 63) stageB((s + 1) << 6, buf ^ 1);

        // warp GEMM on buffer buf: acc += S[16x64] @ B, accz += S @ ones
#pragma unroll
        for (int kc = 0; kc < 4; kc++) {
            uint32_t a[4];
            ldsm4(a[0], a[1], a[2], a[3], aA[buf] + kc * 32);
            uint32_t b[16];
#pragma unroll
            for (int nq = 0; nq < 4; nq++)
                ldsm4(b[nq * 4], b[nq * 4 + 1], b[nq * 4 + 2], b[nq * 4 + 3],
                      bA[buf] + nq * 16 * (BSTR * 2) + kc * 32);
#pragma unroll
            for (int nt = 0; nt < 8; nt++)
                mma16816(acc[nt], a, &b[nt * 2]);
            mma16816(accz, a, bz);
        }

        if (s < 63) genS((s + 1) << 6, buf ^ 1);
    }

    // Z lives in accz col 0 (lanes with lane%4==0): broadcast within row group
    float z0 = __shfl_sync(0xFFFFFFFFu, accz[0], lane & 28);
    float z1 = __shfl_sync(0xFFFFFFFFu, accz[2], lane & 28);
    float inv0 = 1.0f / z0;
    float inv1 = 1.0f / z1;

    // epilogue: normalize, ELU, store. Thread t: rows t/4, t/4+8 (warp-local),
    // cols nt*8 + (t%4)*2 + {0,1}
    {
        int r0 = wid * 16 + (lane >> 2);
        float* o0 = out + (size_t)(i0 + r0) * CF + head * OF + (lane & 3) * 2;
        float* o1 = o0 + 8 * CF;
#pragma unroll
        for (int nt = 0; nt < 8; nt++) {
            float v0 = acc[nt][0] * inv0, v1 = acc[nt][1] * inv0;
            float v2 = acc[nt][2] * inv1, v3 = acc[nt][3] * inv1;
            v0 = v0 > 0.f ? v0 : (expf(v0) - 1.0f);
            v1 = v1 > 0.f ? v1 : (expf(v1) - 1.0f);
            v2 = v2 > 0.f ? v2 : (expf(v2) - 1.0f);
            v3 = v3 > 0.f ? v3 : (expf(v3) - 1.0f);
            *(float2*)(o0 + nt * 8) = make_float2(v0, v1);
            *(float2*)(o1 + nt * 8) = make_float2(v2, v3);
        }
    }
}

// ============================================================
extern "C" void kernel_launch(void* const* d_in, const int* in_sizes, int n_in,
                              void* d_out, int out_size) {
    const float* h   = (const float*)d_in[0];
    const int*   adj = (const int*)d_in[1];
    const float* W   = (const float*)d_in[2];
    const float* a   = (const float*)d_in[3];
    float* out = (float*)d_out;

    k_gemm_wh<<<dim3(8, 32), 256>>>(h, W);
    k_pack<<<NN, 256>>>(adj);
    k_pre<<<NN, 256>>>(a);
    k_transpose<<<dim3(NH, 32), 256>>>();

    cudaFuncSetAttribute(k_gat_mma, cudaFuncAttributeMaxDynamicSharedMemorySize, SM_TOT);
    k_gat_mma<<<dim3(NH, NN / 128), 256, SM_TOT>>>(out);
}

// round 6
// speedup vs baseline: 1.8466x; 1.0365x over previous
#include <cuda_runtime.h>
#include <cuda_fp16.h>
#include <math.h>
#include <stdint.h>

#define NN   4096
#define KF   512     // IN_F
#define CF   512     // OUT_F * N_HEADS
#define NH   8
#define OF   64

// ---- scratch (device globals; no allocation allowed) ----
__device__ float    g_Wh[NN * CF];          // 8 MB fp32 (exact, feeds src/dst)
__device__ __half   g_WhT[NH * OF * NN];    // 4 MB fp16 transposed values [h][f][n]
__device__ unsigned g_bits[NN * 128];       // 2 MB packed adj
__device__ float4   g_attrS[NH * NN];       // (src, Es/16, Es2/16, 0) head-major
__device__ float4   g_attrD[NH * NN];       // (dst, Ed,    Ed2,    0) head-major

__device__ __forceinline__ uint32_t smem_u32(const void* p) {
    uint32_t a;
    asm("{ .reg .u64 t; cvta.to.shared.u64 t, %1; cvt.u32.u64 %0, t; }" : "=r"(a) : "l"(p));
    return a;
}
__device__ __forceinline__ void ldsm4(uint32_t& r0, uint32_t& r1, uint32_t& r2, uint32_t& r3,
                                      uint32_t addr) {
    asm volatile("ldmatrix.sync.aligned.m8n8.x4.shared.b16 {%0,%1,%2,%3}, [%4];"
                 : "=r"(r0), "=r"(r1), "=r"(r2), "=r"(r3) : "r"(addr));
}
__device__ __forceinline__ void mma16816(float* d, const uint32_t* a, const uint32_t* b) {
    asm volatile(
        "mma.sync.aligned.m16n8k16.row.col.f32.f16.f16.f32 "
        "{%0,%1,%2,%3}, {%4,%5,%6,%7}, {%8,%9}, {%0,%1,%2,%3};"
        : "+f"(d[0]), "+f"(d[1]), "+f"(d[2]), "+f"(d[3])
        : "r"(a[0]), "r"(a[1]), "r"(a[2]), "r"(a[3]), "r"(b[0]), "r"(b[1]));
}

// ============================================================
// Kernel A: Wh = h @ W, fp32 tiled GEMM
// ============================================================
__global__ __launch_bounds__(256) void k_gemm_wh(const float* __restrict__ h,
                                                 const float* __restrict__ W) {
    __shared__ float As[16][132];
    __shared__ float Bs[16][68];
    int tid = threadIdx.x;
    int n0 = blockIdx.y * 128;
    int c0 = blockIdx.x * 64;
    float acc[8][4];
#pragma unroll
    for (int r = 0; r < 8; r++)
#pragma unroll
        for (int c = 0; c < 4; c++) acc[r][c] = 0.f;
    int fn = tid & 15, im = tid >> 4;

    for (int k0 = 0; k0 < KF; k0 += 16) {
#pragma unroll
        for (int q = 0; q < 2; q++) {
            int idx = tid + q * 256;
            int n = idx >> 2, kq = (idx & 3) << 2;
            float4 v = *(const float4*)(h + (n0 + n) * KF + k0 + kq);
            As[kq + 0][n] = v.x; As[kq + 1][n] = v.y;
            As[kq + 2][n] = v.z; As[kq + 3][n] = v.w;
        }
        {
            int k = tid >> 4, f4 = (tid & 15) << 2;
            *(float4*)&Bs[k][f4] = *(const float4*)(W + (k0 + k) * CF + c0 + f4);
        }
        __syncthreads();
#pragma unroll
        for (int kk = 0; kk < 16; kk++) {
            float av[8], bv[4];
            *(float4*)&av[0] = *(float4*)&As[kk][im * 8];
            *(float4*)&av[4] = *(float4*)&As[kk][im * 8 + 4];
            *(float4*)&bv[0] = *(float4*)&Bs[kk][fn * 4];
#pragma unroll
            for (int r = 0; r < 8; r++)
#pragma unroll
                for (int c = 0; c < 4; c++)
                    acc[r][c] += av[r] * bv[c];
        }
        __syncthreads();
    }
#pragma unroll
    for (int r = 0; r < 8; r++) {
        float4 v = make_float4(acc[r][0], acc[r][1], acc[r][2], acc[r][3]);
        *(float4*)(g_Wh + (n0 + im * 8 + r) * CF + c0 + fn * 4) = v;
    }
}

// ============================================================
// Kernel PREP (fused pack + pre + transpose), 4096 blocks.
// block b: packs adj row b; computes src/dst attrs for node b;
// blocks 0..255 additionally transpose one 128-row tile to fp16.
// ============================================================
__global__ __launch_bounds__(256) void k_prep(const int* __restrict__ adj,
                                              const float* __restrict__ a) {
    __shared__ __half Ts[64 * 130];
    int b = blockIdx.x;
    int tid = threadIdx.x;
    int w = tid >> 5, lane = tid & 31;

    // ---- pack adj row b ----
#pragma unroll
    for (int q = 0; q < 16; q++) {
        int wd = w * 16 + q;
        int j = wd * 32 + lane;
        unsigned bt = __ballot_sync(0xFFFFFFFFu, adj[(size_t)b * NN + j] > 0);
        if (lane == 0) g_bits[b * 128 + wd] = bt;
    }

    // ---- pre: (node b, head w) ----
    {
        float v0 = g_Wh[b * CF + w * OF + lane];
        float v1 = g_Wh[b * CF + w * OF + 32 + lane];
        float s = v0 * a[lane] + v1 * a[lane + 32];
        float d = v0 * a[64 + lane] + v1 * a[96 + lane];
#pragma unroll
        for (int o = 16; o; o >>= 1) {
            s += __shfl_xor_sync(0xFFFFFFFFu, s, o);
            d += __shfl_xor_sync(0xFFFFFFFFu, d, o);
        }
        if (lane == 0) {
            g_attrS[w * NN + b] = make_float4(s, expf(s) * 0.0625f, expf(0.2f * s) * 0.0625f, 0.f);
            g_attrD[w * NN + b] = make_float4(d, expf(d), expf(0.2f * d), 0.f);
        }
    }

    // ---- transpose (blocks 0..255): head = b&7, rows [(b>>3)*128, +128) ----
    if (b < 256) {
        int h = b & 7, n0 = (b >> 3) * 128;
#pragma unroll
        for (int q = 0; q < 32; q++) {
            int lin = tid + q * 256;
            int r = lin >> 6, c = lin & 63;
            Ts[c * 130 + r] = __float2half(g_Wh[(n0 + r) * CF + h * OF + c]);
        }
        __syncthreads();
#pragma unroll
        for (int q = 0; q < 16; q++) {
            int lin = tid + q * 256;
            int f = lin >> 6, n2 = lin & 63;
            __half2 hv = __halves2half2(Ts[f * 130 + n2 * 2], Ts[f * 130 + n2 * 2 + 1]);
            *(__half2*)&g_WhT[(h * OF + f) * NN + n0 + n2 * 2] = hv;
        }
    }
}

// ============================================================
// Kernel C: fused attention, mma.sync HMMA, single-barrier pipeline,
// register-streaming score generation (low pressure, no spills).
// ============================================================
#define SSTR 72                      // S row stride in halves (144 B)
#define BSTR 72                      // B row stride in halves
#define SBUF 18432                   // 128*72*2 bytes per S buffer
#define BBUF 9216                    // 64*72*2 bytes per B buffer
#define SM_S    0
#define SM_B    36864
#define SM_TOT  55296

__global__ __launch_bounds__(256, 2) void k_gat_mma(float* __restrict__ out) {
    extern __shared__ char sm[];
    uint32_t sb = smem_u32(sm);

    int tid = threadIdx.x, wid = tid >> 5, lane = tid & 31;
    int head = blockIdx.x, i0 = blockIdx.y << 7;

    // score-gen mapping: thread owns rows quad*4..+3, j-group jg (8 j's)
    int jg = tid & 7, quad = tid >> 3;
    float a_src[4], a_es[4], a_es2[4];
#pragma unroll
    for (int r = 0; r < 4; r++) {
        float4 v = g_attrS[head * NN + i0 + quad * 4 + r];
        a_src[r] = v.x; a_es[r] = v.y; a_es2[r] = v.z;
    }
    const float4* attrD = g_attrD + head * NN;
    const unsigned* bitbase = g_bits + (size_t)(i0 + quad * 4) * 128;

    // accumulators: 8 n-tiles (64 cols) + 1 z-tile
    float acc[8][4], accz[4];
#pragma unroll
    for (int nt = 0; nt < 8; nt++)
#pragma unroll
        for (int q = 0; q < 4; q++) acc[nt][q] = 0.f;
#pragma unroll
    for (int q = 0; q < 4; q++) accz[q] = 0.f;

    // ones-column B fragment (col 0 = 1.0): lanes with n==0 (lane<4)
    uint32_t bz[2];
    bz[0] = bz[1] = (lane < 4) ? 0x3C003C00u : 0u;

    // ldmatrix byte addresses per buffer
    uint32_t aA[2], bA[2];
    {
        uint32_t aoff = (wid * 16 + (lane & 15)) * (SSTR * 2) + (lane >> 4) * 16;
        uint32_t boff = (((lane & 7) + ((lane >> 4) & 1) * 8)) * (BSTR * 2)
                      + ((lane >> 3) & 1) * 16;
        aA[0] = sb + SM_S + aoff;          aA[1] = aA[0] + SBUF;
        bA[0] = sb + SM_B + boff;          bA[1] = bA[0] + BBUF;
    }

    // ---- stage B tile (64x64 halves) into buffer bufn ----
    auto stageB = [&](int j0, int bufn) {
        __half* Bd = (__half*)(sm + SM_B + bufn * BBUF);
#pragma unroll
        for (int q = 0; q < 2; q++) {
            int lin = tid + q * 256;
            int f = lin >> 3, c = lin & 7;
            uint4 v = *(const uint4*)&g_WhT[(head * OF + f) * NN + j0 + c * 8];
            *(uint4*)&Bd[f * BSTR + c * 8] = v;
        }
    };
    // ---- generate S tile into buffer bufn; streaming loads, low pressure ----
    auto genS = [&](int j0, int bufn) {
        __half* Sd = (__half*)(sm + SM_S + bufn * SBUF) + (quad * 4) * SSTR + jg * 8;
        int wrd = (j0 >> 5) + (jg >> 2);
        int bitb = (jg & 3) * 8;
        unsigned bw0 = bitbase[wrd];
        unsigned bw1 = bitbase[128 + wrd];
        unsigned bw2 = bitbase[256 + wrd];
        unsigned bw3 = bitbase[384 + wrd];
        const float4* jp = attrD + j0 + jg * 8;
#pragma unroll
        for (int k = 0; k < 4; k++) {
            float4 A0 = jp[2 * k];
            float4 A1 = jp[2 * k + 1];
            unsigned m0 = 1u << (bitb + 2 * k);
            unsigned m1 = m0 << 1;
#pragma unroll
            for (int r = 0; r < 4; r++) {
                unsigned bwr = (r == 0) ? bw0 : (r == 1) ? bw1 : (r == 2) ? bw2 : bw3;
                float t0 = a_src[r] + A0.x;
                float t1 = a_src[r] + A1.x;
                float p0 = (t0 > 0.f) ? a_es[r] * A0.y : a_es2[r] * A0.z;
                float p1 = (t1 > 0.f) ? a_es[r] * A1.y : a_es2[r] * A1.z;
                if (!(bwr & m0)) p0 = 0.f;
                if (!(bwr & m1)) p1 = 0.f;
                *(__half2*)&Sd[r * SSTR + 2 * k] = __floats2half2_rn(p0, p1);
            }
        }
    };

    // prologue: fill buffer 0 for step 0
    stageB(0, 0);
    genS(0, 0);

    for (int s = 0; s < 64; s++) {
        int buf = s & 1;
        __syncthreads();                 // buf ready for mma; buf^1 free for writes
        if (s < 63) stageB((s + 1) << 6, buf ^ 1);

        // warp GEMM on buffer buf: acc += S[16x64] @ B, accz += S @ ones
#pragma unroll
        for (int kc = 0; kc < 4; kc++) {
            uint32_t a[4];
            ldsm4(a[0], a[1], a[2], a[3], aA[buf] + kc * 32);
            uint32_t b[16];
#pragma unroll
            for (int nq = 0; nq < 4; nq++)
                ldsm4(b[nq * 4], b[nq * 4 + 1], b[nq * 4 + 2], b[nq * 4 + 3],
                      bA[buf] + nq * 16 * (BSTR * 2) + kc * 32);
#pragma unroll
            for (int nt = 0; nt < 8; nt++)
                mma16816(acc[nt], a, &b[nt * 2]);
            mma16816(accz, a, bz);
        }

        if (s < 63) genS((s + 1) << 6, buf ^ 1);
    }

    // Z lives in accz col 0 (lanes with lane%4==0): broadcast within row group
    float z0 = __shfl_sync(0xFFFFFFFFu, accz[0], lane & 28);
    float z1 = __shfl_sync(0xFFFFFFFFu, accz[2], lane & 28);
    float inv0 = 1.0f / z0;
    float inv1 = 1.0f / z1;

    // epilogue: normalize, ELU, store
    {
        int r0 = wid * 16 + (lane >> 2);
        float* o0 = out + (size_t)(i0 + r0) * CF + head * OF + (lane & 3) * 2;
        float* o1 = o0 + 8 * CF;
#pragma unroll
        for (int nt = 0; nt < 8; nt++) {
            float v0 = acc[nt][0] * inv0, v1 = acc[nt][1] * inv0;
            float v2 = acc[nt][2] * inv1, v3 = acc[nt][3] * inv1;
            v0 = v0 > 0.f ? v0 : (expf(v0) - 1.0f);
            v1 = v1 > 0.f ? v1 : (expf(v1) - 1.0f);
            v2 = v2 > 0.f ? v2 : (expf(v2) - 1.0f);
            v3 = v3 > 0.f ? v3 : (expf(v3) - 1.0f);
            *(float2*)(o0 + nt * 8) = make_float2(v0, v1);
            *(float2*)(o1 + nt * 8) = make_float2(v2, v3);
        }
    }
}

// ============================================================
extern "C" void kernel_launch(void* const* d_in, const int* in_sizes, int n_in,
                              void* d_out, int out_size) {
    const float* h   = (const float*)d_in[0];
    const int*   adj = (const int*)d_in[1];
    const float* W   = (const float*)d_in[2];
    const float* a   = (const float*)d_in[3];
    float* out = (float*)d_out;

    k_gemm_wh<<<dim3(8, 32), 256>>>(h, W);
    k_prep<<<NN, 256>>>(adj, a);

    cudaFuncSetAttribute(k_gat_mma, cudaFuncAttributeMaxDynamicSharedMemorySize, SM_TOT);
    k_gat_mma<<<dim3(NH, NN / 128), 256, SM_TOT>>>(out);
}

// round 8
// speedup vs baseline: 2.7218x; 1.4739x over previous
#include <cuda_runtime.h>
#include <cuda_fp16.h>
#include <math.h>
#include <stdint.h>

#define NN   4096
#define KF   512     // IN_F
#define CF   512     // OUT_F * N_HEADS
#define NH   8
#define OF   64

// ---- scratch (device globals; no allocation allowed) ----
__device__ float    g_Wh[NN * CF];          // 8 MB fp32
__device__ __half   g_WhT[NH * OF * NN];    // 4 MB fp16 transposed values [h][f][n]
__device__ float4   g_attrS[NH * NN];       // (src, Es/16, Es2/16, 0) head-major
__device__ uint4    g_attrP[NH * (NN / 2)]; // per j-pair: (dst2, Ed2, Ed22, pad) half2-packed
__device__ unsigned g_amask[(size_t)NN * (NN / 2)];  // 32 MB: per (i, j-pair) 16-bit-lane mask

__device__ __forceinline__ uint32_t smem_u32(const void* p) {
    uint32_t a;
    asm("{ .reg .u64 t; cvta.to.shared.u64 t, %1; cvt.u32.u64 %0, t; }" : "=r"(a) : "l"(p));
    return a;
}
__device__ __forceinline__ unsigned h2u(__half2 v) {
    return *reinterpret_cast<unsigned*>(&v);
}
__device__ __forceinline__ void ldsm4(uint32_t& r0, uint32_t& r1, uint32_t& r2, uint32_t& r3,
                                      uint32_t addr) {
    asm volatile("ldmatrix.sync.aligned.m8n8.x4.shared.b16 {%0,%1,%2,%3}, [%4];"
                 : "=r"(r0), "=r"(r1), "=r"(r2), "=r"(r3) : "r"(addr));
}
__device__ __forceinline__ void mma16816(float* d, const uint32_t* a, const uint32_t* b) {
    asm volatile(
        "mma.sync.aligned.m16n8k16.row.col.f32.f16.f16.f32 "
        "{%0,%1,%2,%3}, {%4,%5,%6,%7}, {%8,%9}, {%0,%1,%2,%3};"
        : "+f"(d[0]), "+f"(d[1]), "+f"(d[2]), "+f"(d[3])
        : "r"(a[0]), "r"(a[1]), "r"(a[2]), "r"(a[3]), "r"(b[0]), "r"(b[1]));
}

// ============================================================
// Kernel NOP: aligns ncu's captured launch index onto k_gat_mma
// ============================================================
__global__ void k_nop() {}

// ============================================================
// Kernel A: Wh = h @ W, fp32 tiled GEMM
// ============================================================
__global__ __launch_bounds__(256) void k_gemm_wh(const float* __restrict__ h,
                                                 const float* __restrict__ W) {
    __shared__ float As[16][132];
    __shared__ float Bs[16][68];
    int tid = threadIdx.x;
    int n0 = blockIdx.y * 128;
    int c0 = blockIdx.x * 64;
    float acc[8][4];
#pragma unroll
    for (int r = 0; r < 8; r++)
#pragma unroll
        for (int c = 0; c < 4; c++) acc[r][c] = 0.f;
    int fn = tid & 15, im = tid >> 4;

    for (int k0 = 0; k0 < KF; k0 += 16) {
#pragma unroll
        for (int q = 0; q < 2; q++) {
            int idx = tid + q * 256;
            int n = idx >> 2, kq = (idx & 3) << 2;
            float4 v = *(const float4*)(h + (n0 + n) * KF + k0 + kq);
            As[kq + 0][n] = v.x; As[kq + 1][n] = v.y;
            As[kq + 2][n] = v.z; As[kq + 3][n] = v.w;
        }
        {
            int k = tid >> 4, f4 = (tid & 15) << 2;
            *(float4*)&Bs[k][f4] = *(const float4*)(W + (k0 + k) * CF + c0 + f4);
        }
        __syncthreads();
#pragma unroll
        for (int kk = 0; kk < 16; kk++) {
            float av[8], bv[4];
            *(float4*)&av[0] = *(float4*)&As[kk][im * 8];
            *(float4*)&av[4] = *(float4*)&As[kk][im * 8 + 4];
            *(float4*)&bv[0] = *(float4*)&Bs[kk][fn * 4];
#pragma unroll
            for (int r = 0; r < 8; r++)
#pragma unroll
                for (int c = 0; c < 4; c++)
                    acc[r][c] += av[r] * bv[c];
        }
        __syncthreads();
    }
#pragma unroll
    for (int r = 0; r < 8; r++) {
        float4 v = make_float4(acc[r][0], acc[r][1], acc[r][2], acc[r][3]);
        *(float4*)(g_Wh + (n0 + im * 8 + r) * CF + c0 + fn * 4) = v;
    }
}

// ============================================================
// Kernel PREP: pack+expand adj masks, attrs (fp32 + half2-packed),
// fp16 transpose. 4096 blocks x 256.
// ============================================================
__global__ __launch_bounds__(256) void k_prep(const int* __restrict__ adj,
                                              const float* __restrict__ a) {
    __shared__ __half Ts[64 * 130];
    __shared__ unsigned sbits[128];
    int b = blockIdx.x;
    int tid = threadIdx.x;
    int w = tid >> 5, lane = tid & 31;

    // ---- pack adj row b into smem words ----
#pragma unroll
    for (int q = 0; q < 16; q++) {
        int wd = w * 16 + q;
        int j = wd * 32 + lane;
        unsigned bt = __ballot_sync(0xFFFFFFFFu, adj[(size_t)b * NN + j] > 0);
        if (lane == 0) sbits[wd] = bt;
    }

    // ---- pre: (node b, head w) ----
    {
        float v0 = g_Wh[b * CF + w * OF + lane];
        float v1 = g_Wh[b * CF + w * OF + 32 + lane];
        float s = v0 * a[lane] + v1 * a[lane + 32];
        float d = v0 * a[64 + lane] + v1 * a[96 + lane];
#pragma unroll
        for (int o = 16; o; o >>= 1) {
            s += __shfl_xor_sync(0xFFFFFFFFu, s, o);
            d += __shfl_xor_sync(0xFFFFFFFFu, d, o);
        }
        if (lane == 0) {
            g_attrS[w * NN + b] = make_float4(s, expf(s) * 0.0625f, expf(0.2f * s) * 0.0625f, 0.f);
            // half2-packed per-pair j attrs: this node fills slot (b&1)
            __half* ap = (__half*)(g_attrP + w * (NN / 2) + (b >> 1)) + (b & 1);
            ap[0] = __float2half(d);
            ap[2] = __float2half(expf(d));
            ap[4] = __float2half(expf(0.2f * d));
        }
    }
    __syncthreads();

    // ---- expand adjacency bits to per-pair 32-bit masks ----
#pragma unroll
    for (int q = 0; q < 8; q++) {
        int p = tid + q * 256;                 // pair index 0..2047
        unsigned sel = (sbits[p >> 4] >> ((p & 15) * 2)) & 3u;
        unsigned m = ((sel & 1u) ? 0x0000FFFFu : 0u) | ((sel & 2u) ? 0xFFFF0000u : 0u);
        g_amask[(size_t)b * (NN / 2) + p] = m;
    }

    // ---- transpose (blocks 0..255): head = b&7, rows [(b>>3)*128, +128) ----
    if (b < 256) {
        int h = b & 7, n0 = (b >> 3) * 128;
#pragma unroll
        for (int q = 0; q < 32; q++) {
            int lin = tid + q * 256;
            int r = lin >> 6, c = lin & 63;
            Ts[c * 130 + r] = __float2half(g_Wh[(n0 + r) * CF + h * OF + c]);
        }
        __syncthreads();
#pragma unroll
        for (int q = 0; q < 16; q++) {
            int lin = tid + q * 256;
            int f = lin >> 6, n2 = lin & 63;
            __half2 hv = __halves2half2(Ts[f * 130 + n2 * 2], Ts[f * 130 + n2 * 2 + 1]);
            *(__half2*)&g_WhT[(h * OF + f) * NN + n0 + n2 * 2] = hv;
        }
    }
}

// ============================================================
// Kernel C: fused attention, HMMA pipeline, half2 score generation
// ============================================================
#define SSTR 72
#define BSTR 72
#define SBUF 18432
#define BBUF 9216
#define SM_S    0
#define SM_B    36864
#define SM_TOT  55296

__global__ __launch_bounds__(256, 2) void k_gat_mma(float* __restrict__ out) {
    extern __shared__ char sm[];
    uint32_t sb = smem_u32(sm);

    int tid = threadIdx.x, wid = tid >> 5, lane = tid & 31;
    int head = blockIdx.x, i0 = blockIdx.y << 7;

    // score-gen mapping: thread owns rows quad*4..+3, pair-group jg (4 pairs)
    int jg = tid & 7, quad = tid >> 3;
    __half2 src2[4], es2[4], es22[4];
#pragma unroll
    for (int r = 0; r < 4; r++) {
        float4 v = g_attrS[head * NN + i0 + quad * 4 + r];
        src2[r] = __float2half2_rn(v.x);
        es2[r]  = __float2half2_rn(v.y);
        es22[r] = __float2half2_rn(v.z);
    }
    const uint4* attrP = g_attrP + head * (NN / 2);
    const unsigned* amrow = g_amask + (size_t)(i0 + quad * 4) * (NN / 2);

    float acc[8][4], accz[4];
#pragma unroll
    for (int nt = 0; nt < 8; nt++)
#pragma unroll
        for (int q = 0; q < 4; q++) acc[nt][q] = 0.f;
#pragma unroll
    for (int q = 0; q < 4; q++) accz[q] = 0.f;

    uint32_t bz[2];
    bz[0] = bz[1] = (lane < 4) ? 0x3C003C00u : 0u;

    uint32_t aA[2], bA[2];
    {
        uint32_t aoff = (wid * 16 + (lane & 15)) * (SSTR * 2) + (lane >> 4) * 16;
        uint32_t boff = (((lane & 7) + ((lane >> 4) & 1) * 8)) * (BSTR * 2)
                      + ((lane >> 3) & 1) * 16;
        aA[0] = sb + SM_S + aoff;          aA[1] = aA[0] + SBUF;
        bA[0] = sb + SM_B + boff;          bA[1] = bA[0] + BBUF;
    }

    auto stageB = [&](int j0, int bufn) {
        __half* Bd = (__half*)(sm + SM_B + bufn * BBUF);
#pragma unroll
        for (int q = 0; q < 2; q++) {
            int lin = tid + q * 256;
            int f = lin >> 3, c = lin & 7;
            uint4 v = *(const uint4*)&g_WhT[(head * OF + f) * NN + j0 + c * 8];
            *(uint4*)&Bd[f * BSTR + c * 8] = v;
        }
    };

    // half2 score generation: 4 pairs x 4 rows
    auto genS = [&](int j0, int bufn) {
        uint32_t* Sd = (uint32_t*)((__half*)(sm + SM_S + bufn * SBUF)
                                   + (quad * 4) * SSTR + jg * 8);
        int pb = (j0 >> 1) + jg * 4;           // base pair index
        const uint4* jp = attrP + pb;
        uint4 am0 = *(const uint4*)(amrow + pb);
        uint4 am1 = *(const uint4*)(amrow + (NN / 2) + pb);
        uint4 am2 = *(const uint4*)(amrow + 2 * (NN / 2) + pb);
        uint4 am3 = *(const uint4*)(amrow + 3 * (NN / 2) + pb);
        const __half2 zero2 = __float2half2_rn(0.f);
#pragma unroll
        for (int k = 0; k < 4; k++) {
            uint4 J = jp[k];
            __half2 dst2  = *(__half2*)&J.x;
            __half2 ed2   = *(__half2*)&J.y;
            __half2 ed22  = *(__half2*)&J.z;
            unsigned amk[4] = {
                (&am0.x)[k], (&am1.x)[k], (&am2.x)[k], (&am3.x)[k]
            };
#pragma unroll
            for (int r = 0; r < 4; r++) {
                __half2 t = __hadd2(src2[r], dst2);
                unsigned m = __hgt2_mask(t, zero2);
                unsigned pa = h2u(__hmul2(es2[r], ed2));
                unsigned pbv = h2u(__hmul2(es22[r], ed22));
                unsigned p = ((pa & m) | (pbv & ~m)) & amk[r];
                Sd[r * (SSTR / 2) + k] = p;
            }
        }
    };

    stageB(0, 0);
    genS(0, 0);

    for (int s = 0; s < 64; s++) {
        int buf = s & 1;
        __syncthreads();
        if (s < 63) stageB((s + 1) << 6, buf ^ 1);

#pragma unroll
        for (int kc = 0; kc < 4; kc++) {
            uint32_t a[4];
            ldsm4(a[0], a[1], a[2], a[3], aA[buf] + kc * 32);
            uint32_t b[16];
#pragma unroll
            for (int nq = 0; nq < 4; nq++)
                ldsm4(b[nq * 4], b[nq * 4 + 1], b[nq * 4 + 2], b[nq * 4 + 3],
                      bA[buf] + nq * 16 * (BSTR * 2) + kc * 32);
#pragma unroll
            for (int nt = 0; nt < 8; nt++)
                mma16816(acc[nt], a, &b[nt * 2]);
            mma16816(accz, a, bz);
        }

        if (s < 63) genS((s + 1) << 6, buf ^ 1);
    }

    float z0 = __shfl_sync(0xFFFFFFFFu, accz[0], lane & 28);
    float z1 = __shfl_sync(0xFFFFFFFFu, accz[2], lane & 28);
    float inv0 = 1.0f / z0;
    float inv1 = 1.0f / z1;

    {
        int r0 = wid * 16 + (lane >> 2);
        float* o0 = out + (size_t)(i0 + r0) * CF + head * OF + (lane & 3) * 2;
        float* o1 = o0 + 8 * CF;
#pragma unroll
        for (int nt = 0; nt < 8; nt++) {
            float v0 = acc[nt][0] * inv0, v1 = acc[nt][1] * inv0;
            float v2 = acc[nt][2] * inv1, v3 = acc[nt][3] * inv1;
            v0 = v0 > 0.f ? v0 : (expf(v0) - 1.0f);
            v1 = v1 > 0.f ? v1 : (expf(v1) - 1.0f);
            v2 = v2 > 0.f ? v2 : (expf(v2) - 1.0f);
            v3 = v3 > 0.f ? v3 : (expf(v3) - 1.0f);
            *(float2*)(o0 + nt * 8) = make_float2(v0, v1);
            *(float2*)(o1 + nt * 8) = make_float2(v2, v3);
        }
    }
}

// ============================================================
extern "C" void kernel_launch(void* const* d_in, const int* in_sizes, int n_in,
                              void* d_out, int out_size) {
    const float* h   = (const float*)d_in[0];
    const int*   adj = (const int*)d_in[1];
    const float* W   = (const float*)d_in[2];
    const float* a   = (const float*)d_in[3];
    float* out = (float*)d_out;

    k_nop<<<1, 32>>>();                          // launch-index shim for ncu
    k_gemm_wh<<<dim3(8, 32), 256>>>(h, W);
    k_prep<<<NN, 256>>>(adj, a);

    cudaFuncSetAttribute(k_gat_mma, cudaFuncAttributeMaxDynamicSharedMemorySize, SM_TOT);
    k_gat_mma<<<dim3(NH, NN / 128), 256, SM_TOT>>>(out);
}